// round 10
// baseline (speedup 1.0000x reference)
#include <cuda_runtime.h>
#include <cstdint>

#define NN 50000
#define EE 800000
#define RR 8
#define DIN 64
#define DHID 128
#define DOUT 64
#define NR (NN*RR)
#define LN_EPS 1e-5f

// ---- scratch (device globals; no runtime allocation); 16B-aligned ----
__device__ __align__(16) float g_agg1[(size_t)NN*RR*DIN];
__device__ __align__(16) float g_norm[NR];
__device__ __align__(16) int   g_cnt[NR];
__device__ __align__(16) float g_h[(size_t)NN*DHID];
__device__ __align__(16) float g_hall[(size_t)RR*NN*DOUT];
__device__ __align__(16) float g_oagg[(size_t)NN*DOUT];

__device__ __forceinline__ uint32_t f2tf32(float f) {
    uint32_t v;
    asm("cvt.rna.tf32.f32 %0, %1;" : "=r"(v) : "f"(f));
    return v;
}

__device__ __forceinline__ void mma_tf32(float* c, uint32_t a0, uint32_t a1,
                                         uint32_t a2, uint32_t a3,
                                         uint32_t b0, uint32_t b1) {
    asm volatile(
        "mma.sync.aligned.m16n8k8.row.col.f32.tf32.tf32.f32 "
        "{%0,%1,%2,%3}, {%4,%5,%6,%7}, {%8,%9}, {%0,%1,%2,%3};"
        : "+f"(c[0]), "+f"(c[1]), "+f"(c[2]), "+f"(c[3])
        : "r"(a0), "r"(a1), "r"(a2), "r"(a3), "r"(b0), "r"(b1));
}

__device__ __forceinline__ void red4(float* p, float4 v) {
    asm volatile("red.global.add.v4.f32 [%0], {%1,%2,%3,%4};"
                 :: "l"(p), "f"(v.x), "f"(v.y), "f"(v.z), "f"(v.w) : "memory");
}

__device__ __forceinline__ uint4 cvt4(float4 v) {
    return make_uint4(f2tf32(v.x), f2tf32(v.y), f2tf32(v.z), f2tf32(v.w));
}

// ------------------------------------------------------------------
__global__ void zero_kernel() {
    size_t i = (size_t)blockIdx.x * blockDim.x + threadIdx.x;
    size_t n_agg1 = (size_t)NN * RR * DIN / 4;
    size_t stride = (size_t)gridDim.x * blockDim.x;
    float4 z = make_float4(0.f, 0.f, 0.f, 0.f);
    for (size_t k = i; k < n_agg1; k += stride)
        reinterpret_cast<float4*>(g_agg1)[k] = z;
    for (size_t k = i; k < NR; k += stride)
        g_cnt[k] = 0;
}

__global__ void norm_kernel() {
    int i = blockIdx.x * blockDim.x + threadIdx.x;
    if (i < NR) {
        int c = g_cnt[i];
        g_norm[i] = c > 0 ? 1.0f / (float)c : 0.0f;
    }
}

// ------------------------------------------------------------------
// layer-1 scatter + degree count. One warp owns 32 edges.
__global__ void scatter1_kernel(const float* __restrict__ x,
                                const int* __restrict__ ei,
                                const int* __restrict__ et) {
    unsigned wid = (blockIdx.x * blockDim.x + threadIdx.x) >> 5;
    unsigned lane = threadIdx.x & 31;
    size_t e0 = (size_t)wid * 32;
    if (e0 >= EE) return;
    size_t my_e = e0 + lane;
    int s = ei[my_e];
    int d = ei[EE + my_e];
    int r = et[my_e];
    atomicAdd(&g_cnt[d * RR + r], 1);

    unsigned half = lane >> 4;
    unsigned hl = lane & 15;
#pragma unroll 4
    for (int j = 0; j < 32; j += 2) {
        int sl = j + half;
        int sj = __shfl_sync(0xffffffffu, s, sl);
        int dj = __shfl_sync(0xffffffffu, d, sl);
        int rj = __shfl_sync(0xffffffffu, r, sl);
        float4 v = *reinterpret_cast<const float4*>(x + (size_t)sj * DIN + hl * 4);
        red4(g_agg1 + ((size_t)dj * RR + rj) * DIN + hl * 4, v);
    }
}

// ------------------------------------------------------------------
// layer-1 transform (tf32): h = LN(leaky(Ahat @ [W1;root1] + bias1)); K=576
// BM=128, BN=128; 8 warps as 4(M)x2(N), warp tile 32x64.
// STS.128 everywhere: A stride 36 (group r+4h+i: conflict-free),
// B stride 140 (group 3r+c: conflict-free), B warp loads 4 rows x 8
// consecutive 16B chunks (4 gmem lines per LDG.128).
__global__ __launch_bounds__(256) void transform1_tc(
    const float* __restrict__ x, const float* __restrict__ W1,
    const float* __restrict__ root1, const float* __restrict__ bias1,
    const float* __restrict__ gamma1, const float* __restrict__ beta1) {
    __shared__ __align__(16) uint32_t As[128][36];
    __shared__ __align__(16) uint32_t Bs[32][140];
    __shared__ float red_s[128][2];
    __shared__ float red_q[128][2];
    int tid = threadIdx.x;
    int m0 = blockIdx.x * 128;
    int lane = tid & 31, warp = tid >> 5;
    int warp_m = warp >> 1, warp_n = warp & 1;
    int qr = lane >> 2, qc = lane & 3;

    float acc[2][8][4];
#pragma unroll
    for (int mt = 0; mt < 2; mt++)
#pragma unroll
        for (int t = 0; t < 8; t++)
#pragma unroll
            for (int j = 0; j < 4; j++) acc[mt][t][j] = 0.f;

    int arow = tid >> 1, akoff = (tid & 1) * 16;
    // B mapping: warp covers rows {4(w&3)..+3} x chunks {16(w>>2)..+7}
    int br0 = (lane & 3) + 4 * (warp & 3);        // 0..15 (+16 second group)
    int bc0 = (lane >> 2) + 16 * (warp >> 2);     // chunk 0..7 or 16..23 (+8)

    for (int kk = 0; kk < 576; kk += 32) {
        // ---- A slab ----
        {
            int n = m0 + arow;
            int kg = kk + akoff;
            if (n < NN) {
                if (kg < 512) {
                    float nrm = g_norm[n * 8 + (kg >> 6)];
                    const float4* src =
                        reinterpret_cast<const float4*>(g_agg1 + (size_t)n * 512 + kg);
#pragma unroll
                    for (int i = 0; i < 4; i++) {
                        float4 v = src[i];
                        v.x *= nrm; v.y *= nrm; v.z *= nrm; v.w *= nrm;
                        *reinterpret_cast<uint4*>(&As[arow][akoff + 4*i]) = cvt4(v);
                    }
                } else {
                    const float4* src =
                        reinterpret_cast<const float4*>(x + (size_t)n * 64 + (kg - 512));
#pragma unroll
                    for (int i = 0; i < 4; i++)
                        *reinterpret_cast<uint4*>(&As[arow][akoff + 4*i]) = cvt4(src[i]);
                }
            } else {
                uint4 z = make_uint4(0u, 0u, 0u, 0u);
#pragma unroll
                for (int i = 0; i < 4; i++)
                    *reinterpret_cast<uint4*>(&As[arow][akoff + 4*i]) = z;
            }
        }
        // ---- B slab: 2 row-groups x 2 chunk-halves ----
#pragma unroll
        for (int ri = 0; ri < 2; ri++) {
#pragma unroll
            for (int ci = 0; ci < 2; ci++) {
                int r = br0 + 16 * ri;
                int cc = bc0 + 8 * ci;           // chunk index 0..31
                int kg = kk + r;
                const float* Brow = (kg < 512) ? (W1 + (size_t)kg * 128)
                                               : (root1 + (size_t)(kg - 512) * 128);
                float4 v = *reinterpret_cast<const float4*>(Brow + cc * 4);
                *reinterpret_cast<uint4*>(&Bs[r][cc * 4]) = cvt4(v);
            }
        }
        __syncthreads();
#pragma unroll
        for (int k8 = 0; k8 < 4; k8++) {
            int k0 = k8 * 8;
            uint32_t a[2][4];
#pragma unroll
            for (int mt = 0; mt < 2; mt++) {
                int ar = warp_m * 32 + mt * 16 + qr;
                a[mt][0] = As[ar][k0 + qc];
                a[mt][1] = As[ar + 8][k0 + qc];
                a[mt][2] = As[ar][k0 + qc + 4];
                a[mt][3] = As[ar + 8][k0 + qc + 4];
            }
#pragma unroll
            for (int t = 0; t < 8; t++) {
                int cn = warp_n * 64 + t * 8 + qr;
                uint32_t b0 = Bs[k0 + qc][cn];
                uint32_t b1 = Bs[k0 + qc + 4][cn];
                mma_tf32(acc[0][t], a[0][0], a[0][1], a[0][2], a[0][3], b0, b1);
                mma_tf32(acc[1][t], a[1][0], a[1][1], a[1][2], a[1][3], b0, b1);
            }
        }
        __syncthreads();
    }

    // ---- epilogue: bias + LeakyReLU; cross-warp LN(128) via smem partials ----
#pragma unroll
    for (int mt = 0; mt < 2; mt++) {
        float s[2] = {0.f, 0.f}, q[2] = {0.f, 0.f};
#pragma unroll
        for (int t = 0; t < 8; t++) {
            int c = warp_n * 64 + t * 8 + 2 * qc;
            float b0v = bias1[c], b1v = bias1[c + 1];
            float u;
            u = acc[mt][t][0] + b0v; u = u >= 0.f ? u : 0.2f * u; acc[mt][t][0] = u; s[0] += u; q[0] += u * u;
            u = acc[mt][t][1] + b1v; u = u >= 0.f ? u : 0.2f * u; acc[mt][t][1] = u; s[0] += u; q[0] += u * u;
            u = acc[mt][t][2] + b0v; u = u >= 0.f ? u : 0.2f * u; acc[mt][t][2] = u; s[1] += u; q[1] += u * u;
            u = acc[mt][t][3] + b1v; u = u >= 0.f ? u : 0.2f * u; acc[mt][t][3] = u; s[1] += u; q[1] += u * u;
        }
#pragma unroll
        for (int off = 1; off <= 2; off <<= 1) {
            s[0] += __shfl_xor_sync(0xffffffffu, s[0], off);
            q[0] += __shfl_xor_sync(0xffffffffu, q[0], off);
            s[1] += __shfl_xor_sync(0xffffffffu, s[1], off);
            q[1] += __shfl_xor_sync(0xffffffffu, q[1], off);
        }
        if (qc == 0) {
            int lr = warp_m * 32 + mt * 16 + qr;
            red_s[lr][warp_n] = s[0]; red_q[lr][warp_n] = q[0];
            red_s[lr + 8][warp_n] = s[1]; red_q[lr + 8][warp_n] = q[1];
        }
    }
    __syncthreads();
#pragma unroll
    for (int mt = 0; mt < 2; mt++) {
#pragma unroll
        for (int h = 0; h < 2; h++) {
            int lr = warp_m * 32 + mt * 16 + qr + 8 * h;
            int gm = m0 + lr;
            float S = red_s[lr][0] + red_s[lr][1];
            float Q = red_q[lr][0] + red_q[lr][1];
            float mu = S * (1.f / 128.f);
            float rstd = rsqrtf(Q * (1.f / 128.f) - mu * mu + LN_EPS);
            if (gm < NN) {
#pragma unroll
                for (int t = 0; t < 8; t++) {
                    int c = warp_n * 64 + t * 8 + 2 * qc;
                    float g0 = gamma1[c], g1 = gamma1[c + 1];
                    float e0 = beta1[c], e1 = beta1[c + 1];
                    *reinterpret_cast<float2*>(&g_h[(size_t)gm * 128 + c]) =
                        make_float2((acc[mt][t][2*h] - mu) * rstd * g0 + e0,
                                    (acc[mt][t][2*h+1] - mu) * rstd * g1 + e1);
                }
            }
        }
    }
}

// ------------------------------------------------------------------
// layer-2 transform (tf32): grid.y = r in [0,9). r<8: hall[r]=h@W2_r; r==8:
// g_oagg = h@root2. 256 threads, 8 warps as 4(M)x2(N), warp tile 32x32.
// B stride 76 (304B = 19x16: group 3r+c), 4rows x 8chunk warp mapping.
__global__ __launch_bounds__(256) void transform2_tc(const float* __restrict__ W2,
                                                     const float* __restrict__ root2) {
    __shared__ __align__(16) uint32_t As[128][36];
    __shared__ __align__(16) uint32_t Bs[32][76];
    int tid = threadIdx.x;
    int m0 = blockIdx.x * 128;
    int r = blockIdx.y;
    const float* Wr = (r < RR) ? (W2 + (size_t)r * 128 * 64) : root2;
    int lane = tid & 31, warp = tid >> 5;
    int warp_m = warp >> 1, warp_n = warp & 1;
    int qr = lane >> 2, qc = lane & 3;

    float acc[2][4][4];
#pragma unroll
    for (int mt = 0; mt < 2; mt++)
#pragma unroll
        for (int t = 0; t < 4; t++)
#pragma unroll
            for (int j = 0; j < 4; j++) acc[mt][t][j] = 0.f;

    int arow = tid >> 1, akoff = (tid & 1) * 16;
    int br0 = (lane & 3) + 4 * (warp & 3);     // row 0..15 (+16)
    int bc  = (lane >> 2) + 8 * (warp >> 2);   // chunk 0..15 (64 f32 = 16 chunks)

    for (int kk = 0; kk < 128; kk += 32) {
        {
            int n = m0 + arow;
            if (n < NN) {
                const float4* src =
                    reinterpret_cast<const float4*>(g_h + (size_t)n * 128 + kk + akoff);
#pragma unroll
                for (int i = 0; i < 4; i++)
                    *reinterpret_cast<uint4*>(&As[arow][akoff + 4*i]) = cvt4(src[i]);
            } else {
                uint4 z = make_uint4(0u, 0u, 0u, 0u);
#pragma unroll
                for (int i = 0; i < 4; i++)
                    *reinterpret_cast<uint4*>(&As[arow][akoff + 4*i]) = z;
            }
        }
#pragma unroll
        for (int ri = 0; ri < 2; ri++) {
            int rr = br0 + 16 * ri;
            float4 v = *reinterpret_cast<const float4*>(
                Wr + (size_t)(kk + rr) * 64 + bc * 4);
            *reinterpret_cast<uint4*>(&Bs[rr][bc * 4]) = cvt4(v);
        }
        __syncthreads();
#pragma unroll
        for (int k8 = 0; k8 < 4; k8++) {
            int k0 = k8 * 8;
            uint32_t a[2][4];
#pragma unroll
            for (int mt = 0; mt < 2; mt++) {
                int ar = warp_m * 32 + mt * 16 + qr;
                a[mt][0] = As[ar][k0 + qc];
                a[mt][1] = As[ar + 8][k0 + qc];
                a[mt][2] = As[ar][k0 + qc + 4];
                a[mt][3] = As[ar + 8][k0 + qc + 4];
            }
#pragma unroll
            for (int t = 0; t < 4; t++) {
                int cn = warp_n * 32 + t * 8 + qr;
                uint32_t b0 = Bs[k0 + qc][cn];
                uint32_t b1 = Bs[k0 + qc + 4][cn];
                mma_tf32(acc[0][t], a[0][0], a[0][1], a[0][2], a[0][3], b0, b1);
                mma_tf32(acc[1][t], a[1][0], a[1][1], a[1][2], a[1][3], b0, b1);
            }
        }
        __syncthreads();
    }

    float* dst = (r < RR) ? (g_hall + (size_t)r * NN * 64) : g_oagg;
#pragma unroll
    for (int mt = 0; mt < 2; mt++) {
        int r1 = m0 + warp_m * 32 + mt * 16 + qr;
        int r2 = r1 + 8;
#pragma unroll
        for (int t = 0; t < 4; t++) {
            int c = warp_n * 32 + t * 8 + 2 * qc;
            if (r1 < NN)
                *reinterpret_cast<float2*>(dst + (size_t)r1 * 64 + c) =
                    make_float2(acc[mt][t][0], acc[mt][t][1]);
            if (r2 < NN)
                *reinterpret_cast<float2*>(dst + (size_t)r2 * 64 + c) =
                    make_float2(acc[mt][t][2], acc[mt][t][3]);
        }
    }
}

// ------------------------------------------------------------------
// layer-2 scatter (warp-cooperative): oagg[dst,:] += norm * hall[rel,src,:]
__global__ void scatter2_kernel(const int* __restrict__ ei,
                                const int* __restrict__ et) {
    unsigned wid = (blockIdx.x * blockDim.x + threadIdx.x) >> 5;
    unsigned lane = threadIdx.x & 31;
    size_t e0 = (size_t)wid * 32;
    if (e0 >= EE) return;
    size_t my_e = e0 + lane;
    int s = ei[my_e];
    int d = ei[EE + my_e];
    int r = et[my_e];
    float nrm = g_norm[d * RR + r];

    unsigned half = lane >> 4;
    unsigned hl = lane & 15;
#pragma unroll 4
    for (int j = 0; j < 32; j += 2) {
        int sl = j + half;
        int sj = __shfl_sync(0xffffffffu, s, sl);
        int dj = __shfl_sync(0xffffffffu, d, sl);
        int rj = __shfl_sync(0xffffffffu, r, sl);
        float nj = __shfl_sync(0xffffffffu, nrm, sl);
        float4 v = *reinterpret_cast<const float4*>(
            g_hall + ((size_t)rj * NN + sj) * 64 + hl * 4);
        v.x *= nj; v.y *= nj; v.z *= nj; v.w *= nj;
        red4(g_oagg + (size_t)dj * 64 + hl * 4, v);
    }
}

// ------------------------------------------------------------------
// final: out = LN(oagg + bias2)
__global__ void final_ln(const float* __restrict__ bias2,
                         const float* __restrict__ gamma2,
                         const float* __restrict__ beta2,
                         float* __restrict__ out) {
    int t = blockIdx.x * blockDim.x + threadIdx.x;
    int n = t >> 4, hl = t & 15;
    if (n >= NN) return;
    float4 v = *reinterpret_cast<const float4*>(g_oagg + (size_t)n * 64 + hl * 4);
    float4 b = *reinterpret_cast<const float4*>(bias2 + hl * 4);
    v.x += b.x; v.y += b.y; v.z += b.z; v.w += b.w;
    float s = v.x + v.y + v.z + v.w;
    float q = v.x * v.x + v.y * v.y + v.z * v.z + v.w * v.w;
#pragma unroll
    for (int off = 8; off; off >>= 1) {
        s += __shfl_xor_sync(0xffffffffu, s, off);
        q += __shfl_xor_sync(0xffffffffu, q, off);
    }
    float mu = s * (1.f / 64.f);
    float rstd = rsqrtf(q * (1.f / 64.f) - mu * mu + LN_EPS);
    float4 g = *reinterpret_cast<const float4*>(gamma2 + hl * 4);
    float4 e = *reinterpret_cast<const float4*>(beta2 + hl * 4);
    float4 o;
    o.x = (v.x - mu) * rstd * g.x + e.x;
    o.y = (v.y - mu) * rstd * g.y + e.y;
    o.z = (v.z - mu) * rstd * g.z + e.z;
    o.w = (v.w - mu) * rstd * g.w + e.w;
    *reinterpret_cast<float4*>(out + (size_t)n * 64 + hl * 4) = o;
}

// ------------------------------------------------------------------
extern "C" void kernel_launch(void* const* d_in, const int* in_sizes, int n_in,
                              void* d_out, int out_size) {
    const float* x      = (const float*)d_in[0];
    const int*   ei     = (const int*)d_in[1];
    const int*   et     = (const int*)d_in[2];
    const float* W1     = (const float*)d_in[3];
    const float* root1  = (const float*)d_in[4];
    const float* bias1  = (const float*)d_in[5];
    const float* gamma1 = (const float*)d_in[6];
    const float* beta1  = (const float*)d_in[7];
    const float* W2     = (const float*)d_in[8];
    const float* root2  = (const float*)d_in[9];
    const float* bias2  = (const float*)d_in[10];
    const float* gamma2 = (const float*)d_in[11];
    const float* beta2  = (const float*)d_in[12];
    float*       out    = (float*)d_out;

    zero_kernel<<<1024, 256>>>();
    scatter1_kernel<<<(EE + 255) / 256, 256>>>(x, ei, et);
    norm_kernel<<<(NR + 255) / 256, 256>>>();
    int mblocks = (NN + 127) / 128;
    transform1_tc<<<mblocks, 256>>>(x, W1, root1, bias1, gamma1, beta1);
    dim3 g2(mblocks, RR + 1);
    transform2_tc<<<g2, 256>>>(W2, root2);
    scatter2_kernel<<<(EE + 255) / 256, 256>>>(ei, et);
    final_ln<<<(NN * 16 + 255) / 256, 256>>>(bias2, gamma2, beta2, out);
}

// round 11
// speedup vs baseline: 1.1388x; 1.1388x over previous
#include <cuda_runtime.h>
#include <cstdint>

#define NN 50000
#define EE 800000
#define RR 8
#define DIN 64
#define DHID 128
#define DOUT 64
#define NR (NN*RR)
#define LN_EPS 1e-5f

// ---- scratch (device globals; no runtime allocation); 16B-aligned ----
__device__ __align__(16) float g_agg1[(size_t)NN*RR*DIN];  // pre-normalized sums
__device__ __align__(16) float g_norm[NR];
__device__ __align__(16) int   g_cnt[NR];
__device__ __align__(16) float g_h[(size_t)NN*DHID];
__device__ __align__(16) float g_hall[(size_t)RR*NN*DOUT];
__device__ __align__(16) float g_oagg[(size_t)NN*DOUT];

__device__ __forceinline__ uint32_t f2tf32(float f) {
    uint32_t v;
    asm("cvt.rna.tf32.f32 %0, %1;" : "=r"(v) : "f"(f));
    return v;
}

__device__ __forceinline__ void mma_tf32(float* c, uint32_t a0, uint32_t a1,
                                         uint32_t a2, uint32_t a3,
                                         uint32_t b0, uint32_t b1) {
    asm volatile(
        "mma.sync.aligned.m16n8k8.row.col.f32.tf32.tf32.f32 "
        "{%0,%1,%2,%3}, {%4,%5,%6,%7}, {%8,%9}, {%0,%1,%2,%3};"
        : "+f"(c[0]), "+f"(c[1]), "+f"(c[2]), "+f"(c[3])
        : "r"(a0), "r"(a1), "r"(a2), "r"(a3), "r"(b0), "r"(b1));
}

__device__ __forceinline__ void red4(float* p, float4 v) {
    asm volatile("red.global.add.v4.f32 [%0], {%1,%2,%3,%4};"
                 :: "l"(p), "f"(v.x), "f"(v.y), "f"(v.z), "f"(v.w) : "memory");
}

// 16B async copy; pred=false -> zero-fill (src-size 0)
__device__ __forceinline__ void cp16(void* smem, const void* gmem, bool pred) {
    uint32_t s = (uint32_t)__cvta_generic_to_shared(smem);
    int sz = pred ? 16 : 0;
    asm volatile("cp.async.cg.shared.global [%0], [%1], 16, %2;"
                 :: "r"(s), "l"(gmem), "r"(sz));
}
__device__ __forceinline__ void cp_commit() {
    asm volatile("cp.async.commit_group;");
}

// ------------------------------------------------------------------
__global__ void zero_kernel() {
    size_t i = (size_t)blockIdx.x * blockDim.x + threadIdx.x;
    size_t n_agg1 = (size_t)NN * RR * DIN / 4;
    size_t stride = (size_t)gridDim.x * blockDim.x;
    float4 z = make_float4(0.f, 0.f, 0.f, 0.f);
    for (size_t k = i; k < n_agg1; k += stride)
        reinterpret_cast<float4*>(g_agg1)[k] = z;
    for (size_t k = i; k < NR; k += stride)
        g_cnt[k] = 0;
}

__global__ void count_kernel(const int* __restrict__ ei,
                             const int* __restrict__ et) {
    int e = blockIdx.x * blockDim.x + threadIdx.x;
    if (e < EE) atomicAdd(&g_cnt[ei[EE + e] * RR + et[e]], 1);
}

__global__ void norm_kernel() {
    int i = blockIdx.x * blockDim.x + threadIdx.x;
    if (i < NR) {
        int c = g_cnt[i];
        g_norm[i] = c > 0 ? 1.0f / (float)c : 0.0f;
    }
}

// ------------------------------------------------------------------
// layer-1 scatter with norm folded in: agg1[dst,rel,:] += norm * x[src,:]
__global__ void scatter1_kernel(const float* __restrict__ x,
                                const int* __restrict__ ei,
                                const int* __restrict__ et) {
    unsigned wid = (blockIdx.x * blockDim.x + threadIdx.x) >> 5;
    unsigned lane = threadIdx.x & 31;
    size_t e0 = (size_t)wid * 32;
    if (e0 >= EE) return;
    size_t my_e = e0 + lane;
    int s = ei[my_e];
    int d = ei[EE + my_e];
    int r = et[my_e];
    float nrm = g_norm[d * RR + r];

    unsigned half = lane >> 4;
    unsigned hl = lane & 15;
#pragma unroll 4
    for (int j = 0; j < 32; j += 2) {
        int sl = j + half;
        int sj = __shfl_sync(0xffffffffu, s, sl);
        int dj = __shfl_sync(0xffffffffu, d, sl);
        int rj = __shfl_sync(0xffffffffu, r, sl);
        float nj = __shfl_sync(0xffffffffu, nrm, sl);
        float4 v = *reinterpret_cast<const float4*>(x + (size_t)sj * DIN + hl * 4);
        v.x *= nj; v.y *= nj; v.z *= nj; v.w *= nj;
        red4(g_agg1 + ((size_t)dj * RR + rj) * DIN + hl * 4, v);
    }
}

// ------------------------------------------------------------------
// layer-1 transform (tf32, cp.async 2-stage): h = LN(leaky(Ahat@[W1;root1]+bias1))
// Ahat[n, k<512] = g_agg1 (pre-normalized); Ahat[n, 512+d] = x[n,d]. K=576.
// BM=128, BN=128, BK=16 (36 slabs). fp32 in smem; tf32 cvt at fragment load.
__global__ __launch_bounds__(256) void transform1_tc(
    const float* __restrict__ x, const float* __restrict__ W1,
    const float* __restrict__ root1, const float* __restrict__ bias1,
    const float* __restrict__ gamma1, const float* __restrict__ beta1) {
    __shared__ __align__(16) float As[2][128][20];   // stride 20: LDS conflict-free
    __shared__ __align__(16) float Bs[2][16][136];   // stride 136: LDS conflict-free
    __shared__ float red_s[128][2];
    __shared__ float red_q[128][2];
    int tid = threadIdx.x;
    int m0 = blockIdx.x * 128;
    int lane = tid & 31, warp = tid >> 5;
    int warp_m = warp >> 1, warp_n = warp & 1;
    int qr = lane >> 2, qc = lane & 3;

    float acc[2][8][4];
#pragma unroll
    for (int mt = 0; mt < 2; mt++)
#pragma unroll
        for (int t = 0; t < 8; t++)
#pragma unroll
            for (int j = 0; j < 4; j++) acc[mt][t][j] = 0.f;

    // cp.async thread mapping
    int a_row = tid >> 1, a_c0 = (tid & 1) * 2;          // A: 2 chunks of 16B
    int b_row = tid >> 4, b_c0 = (tid & 15) * 2;         // B: 2 chunks of 16B
    bool a_valid = (m0 + a_row) < NN;

    auto issue = [&](int slab, int buf) {
        // A: rows m0..m0+127, floats [slab*16 + a_c*4, +4)
#pragma unroll
        for (int i = 0; i < 2; i++) {
            int kg = slab * 16 + (a_c0 + i) * 4;
            const float* src = (kg < 512)
                ? g_agg1 + (size_t)(m0 + a_row) * 512 + kg
                : x + (size_t)(m0 + a_row) * 64 + (kg - 512);
            cp16(&As[buf][a_row][(a_c0 + i) * 4], src, a_valid);
        }
        // B: k-rows slab*16..+15, all 128 cols
        {
            int kg = slab * 16 + b_row;
            const float* Brow = (kg < 512) ? (W1 + (size_t)kg * 128)
                                           : (root1 + (size_t)(kg - 512) * 128);
#pragma unroll
            for (int i = 0; i < 2; i++)
                cp16(&Bs[buf][b_row][(b_c0 + i) * 4], Brow + (b_c0 + i) * 4, true);
        }
        cp_commit();
    };

    const int NS = 36;
    issue(0, 0);
    for (int s = 0; s < NS; s++) {
        int buf = s & 1;
        if (s + 1 < NS) {
            issue(s + 1, (s + 1) & 1);
            asm volatile("cp.async.wait_group 1;");
        } else {
            asm volatile("cp.async.wait_group 0;");
        }
        __syncthreads();
#pragma unroll
        for (int k8 = 0; k8 < 2; k8++) {
            int k0 = k8 * 8;
            uint32_t a[2][4];
#pragma unroll
            for (int mt = 0; mt < 2; mt++) {
                int ar = warp_m * 32 + mt * 16 + qr;
                a[mt][0] = f2tf32(As[buf][ar][k0 + qc]);
                a[mt][1] = f2tf32(As[buf][ar + 8][k0 + qc]);
                a[mt][2] = f2tf32(As[buf][ar][k0 + qc + 4]);
                a[mt][3] = f2tf32(As[buf][ar + 8][k0 + qc + 4]);
            }
#pragma unroll
            for (int t = 0; t < 8; t++) {
                int cn = warp_n * 64 + t * 8 + qr;
                uint32_t b0 = f2tf32(Bs[buf][k0 + qc][cn]);
                uint32_t b1 = f2tf32(Bs[buf][k0 + qc + 4][cn]);
                mma_tf32(acc[0][t], a[0][0], a[0][1], a[0][2], a[0][3], b0, b1);
                mma_tf32(acc[1][t], a[1][0], a[1][1], a[1][2], a[1][3], b0, b1);
            }
        }
        __syncthreads();
    }

    // ---- epilogue: bias + LeakyReLU; cross-warp LN(128) ----
#pragma unroll
    for (int mt = 0; mt < 2; mt++) {
        float s[2] = {0.f, 0.f}, q[2] = {0.f, 0.f};
#pragma unroll
        for (int t = 0; t < 8; t++) {
            int c = warp_n * 64 + t * 8 + 2 * qc;
            float b0v = bias1[c], b1v = bias1[c + 1];
            float u;
            u = acc[mt][t][0] + b0v; u = u >= 0.f ? u : 0.2f * u; acc[mt][t][0] = u; s[0] += u; q[0] += u * u;
            u = acc[mt][t][1] + b1v; u = u >= 0.f ? u : 0.2f * u; acc[mt][t][1] = u; s[0] += u; q[0] += u * u;
            u = acc[mt][t][2] + b0v; u = u >= 0.f ? u : 0.2f * u; acc[mt][t][2] = u; s[1] += u; q[1] += u * u;
            u = acc[mt][t][3] + b1v; u = u >= 0.f ? u : 0.2f * u; acc[mt][t][3] = u; s[1] += u; q[1] += u * u;
        }
#pragma unroll
        for (int off = 1; off <= 2; off <<= 1) {
            s[0] += __shfl_xor_sync(0xffffffffu, s[0], off);
            q[0] += __shfl_xor_sync(0xffffffffu, q[0], off);
            s[1] += __shfl_xor_sync(0xffffffffu, s[1], off);
            q[1] += __shfl_xor_sync(0xffffffffu, q[1], off);
        }
        if (qc == 0) {
            int lr = warp_m * 32 + mt * 16 + qr;
            red_s[lr][warp_n] = s[0]; red_q[lr][warp_n] = q[0];
            red_s[lr + 8][warp_n] = s[1]; red_q[lr + 8][warp_n] = q[1];
        }
    }
    __syncthreads();
#pragma unroll
    for (int mt = 0; mt < 2; mt++) {
#pragma unroll
        for (int h = 0; h < 2; h++) {
            int lr = warp_m * 32 + mt * 16 + qr + 8 * h;
            int gm = m0 + lr;
            float S = red_s[lr][0] + red_s[lr][1];
            float Q = red_q[lr][0] + red_q[lr][1];
            float mu = S * (1.f / 128.f);
            float rstd = rsqrtf(Q * (1.f / 128.f) - mu * mu + LN_EPS);
            if (gm < NN) {
#pragma unroll
                for (int t = 0; t < 8; t++) {
                    int c = warp_n * 64 + t * 8 + 2 * qc;
                    float g0 = gamma1[c], g1 = gamma1[c + 1];
                    float e0 = beta1[c], e1 = beta1[c + 1];
                    *reinterpret_cast<float2*>(&g_h[(size_t)gm * 128 + c]) =
                        make_float2((acc[mt][t][2*h] - mu) * rstd * g0 + e0,
                                    (acc[mt][t][2*h+1] - mu) * rstd * g1 + e1);
                }
            }
        }
    }
}

// ------------------------------------------------------------------
// layer-2 transform (tf32, cp.async 2-stage): grid.y = r in [0,9).
// r<8: hall[r]=h@W2_r; r==8: g_oagg=h@root2. BK=16 (8 slabs), warp tile 32x32.
__global__ __launch_bounds__(256) void transform2_tc(const float* __restrict__ W2,
                                                     const float* __restrict__ root2) {
    __shared__ __align__(16) float As[2][128][20];
    __shared__ __align__(16) float Bs[2][16][72];
    int tid = threadIdx.x;
    int m0 = blockIdx.x * 128;
    int r = blockIdx.y;
    const float* Wr = (r < RR) ? (W2 + (size_t)r * 128 * 64) : root2;
    int lane = tid & 31, warp = tid >> 5;
    int warp_m = warp >> 1, warp_n = warp & 1;
    int qr = lane >> 2, qc = lane & 3;

    float acc[2][4][4];
#pragma unroll
    for (int mt = 0; mt < 2; mt++)
#pragma unroll
        for (int t = 0; t < 4; t++)
#pragma unroll
            for (int j = 0; j < 4; j++) acc[mt][t][j] = 0.f;

    int a_row = tid >> 1, a_c0 = (tid & 1) * 2;
    int b_row = tid >> 4, b_c = tid & 15;        // 16 chunks of 16B per row
    bool a_valid = (m0 + a_row) < NN;

    auto issue = [&](int slab, int buf) {
#pragma unroll
        for (int i = 0; i < 2; i++) {
            int kg = slab * 16 + (a_c0 + i) * 4;
            cp16(&As[buf][a_row][(a_c0 + i) * 4],
                 g_h + (size_t)(m0 + a_row) * 128 + kg, a_valid);
        }
        int kg = slab * 16 + b_row;
        cp16(&Bs[buf][b_row][b_c * 4], Wr + (size_t)kg * 64 + b_c * 4, true);
        cp_commit();
    };

    const int NS = 8;
    issue(0, 0);
    for (int s = 0; s < NS; s++) {
        int buf = s & 1;
        if (s + 1 < NS) {
            issue(s + 1, (s + 1) & 1);
            asm volatile("cp.async.wait_group 1;");
        } else {
            asm volatile("cp.async.wait_group 0;");
        }
        __syncthreads();
#pragma unroll
        for (int k8 = 0; k8 < 2; k8++) {
            int k0 = k8 * 8;
            uint32_t a[2][4];
#pragma unroll
            for (int mt = 0; mt < 2; mt++) {
                int ar = warp_m * 32 + mt * 16 + qr;
                a[mt][0] = f2tf32(As[buf][ar][k0 + qc]);
                a[mt][1] = f2tf32(As[buf][ar + 8][k0 + qc]);
                a[mt][2] = f2tf32(As[buf][ar][k0 + qc + 4]);
                a[mt][3] = f2tf32(As[buf][ar + 8][k0 + qc + 4]);
            }
#pragma unroll
            for (int t = 0; t < 4; t++) {
                int cn = warp_n * 32 + t * 8 + qr;
                uint32_t b0 = f2tf32(Bs[buf][k0 + qc][cn]);
                uint32_t b1 = f2tf32(Bs[buf][k0 + qc + 4][cn]);
                mma_tf32(acc[0][t], a[0][0], a[0][1], a[0][2], a[0][3], b0, b1);
                mma_tf32(acc[1][t], a[1][0], a[1][1], a[1][2], a[1][3], b0, b1);
            }
        }
        __syncthreads();
    }

    float* dst = (r < RR) ? (g_hall + (size_t)r * NN * 64) : g_oagg;
#pragma unroll
    for (int mt = 0; mt < 2; mt++) {
        int r1 = m0 + warp_m * 32 + mt * 16 + qr;
        int r2 = r1 + 8;
#pragma unroll
        for (int t = 0; t < 4; t++) {
            int c = warp_n * 32 + t * 8 + 2 * qc;
            if (r1 < NN)
                *reinterpret_cast<float2*>(dst + (size_t)r1 * 64 + c) =
                    make_float2(acc[mt][t][0], acc[mt][t][1]);
            if (r2 < NN)
                *reinterpret_cast<float2*>(dst + (size_t)r2 * 64 + c) =
                    make_float2(acc[mt][t][2], acc[mt][t][3]);
        }
    }
}

// ------------------------------------------------------------------
// layer-2 scatter (warp-cooperative): oagg[dst,:] += norm * hall[rel,src,:]
__global__ void scatter2_kernel(const int* __restrict__ ei,
                                const int* __restrict__ et) {
    unsigned wid = (blockIdx.x * blockDim.x + threadIdx.x) >> 5;
    unsigned lane = threadIdx.x & 31;
    size_t e0 = (size_t)wid * 32;
    if (e0 >= EE) return;
    size_t my_e = e0 + lane;
    int s = ei[my_e];
    int d = ei[EE + my_e];
    int r = et[my_e];
    float nrm = g_norm[d * RR + r];

    unsigned half = lane >> 4;
    unsigned hl = lane & 15;
#pragma unroll 4
    for (int j = 0; j < 32; j += 2) {
        int sl = j + half;
        int sj = __shfl_sync(0xffffffffu, s, sl);
        int dj = __shfl_sync(0xffffffffu, d, sl);
        int rj = __shfl_sync(0xffffffffu, r, sl);
        float nj = __shfl_sync(0xffffffffu, nrm, sl);
        float4 v = *reinterpret_cast<const float4*>(
            g_hall + ((size_t)rj * NN + sj) * 64 + hl * 4);
        v.x *= nj; v.y *= nj; v.z *= nj; v.w *= nj;
        red4(g_oagg + (size_t)dj * 64 + hl * 4, v);
    }
}

// ------------------------------------------------------------------
// final: out = LN(oagg + bias2)
__global__ void final_ln(const float* __restrict__ bias2,
                         const float* __restrict__ gamma2,
                         const float* __restrict__ beta2,
                         float* __restrict__ out) {
    int t = blockIdx.x * blockDim.x + threadIdx.x;
    int n = t >> 4, hl = t & 15;
    if (n >= NN) return;
    float4 v = *reinterpret_cast<const float4*>(g_oagg + (size_t)n * 64 + hl * 4);
    float4 b = *reinterpret_cast<const float4*>(bias2 + hl * 4);
    v.x += b.x; v.y += b.y; v.z += b.z; v.w += b.w;
    float s = v.x + v.y + v.z + v.w;
    float q = v.x * v.x + v.y * v.y + v.z * v.z + v.w * v.w;
#pragma unroll
    for (int off = 8; off; off >>= 1) {
        s += __shfl_xor_sync(0xffffffffu, s, off);
        q += __shfl_xor_sync(0xffffffffu, q, off);
    }
    float mu = s * (1.f / 64.f);
    float rstd = rsqrtf(q * (1.f / 64.f) - mu * mu + LN_EPS);
    float4 g = *reinterpret_cast<const float4*>(gamma2 + hl * 4);
    float4 e = *reinterpret_cast<const float4*>(beta2 + hl * 4);
    float4 o;
    o.x = (v.x - mu) * rstd * g.x + e.x;
    o.y = (v.y - mu) * rstd * g.y + e.y;
    o.z = (v.z - mu) * rstd * g.z + e.z;
    o.w = (v.w - mu) * rstd * g.w + e.w;
    *reinterpret_cast<float4*>(out + (size_t)n * 64 + hl * 4) = o;
}

// ------------------------------------------------------------------
extern "C" void kernel_launch(void* const* d_in, const int* in_sizes, int n_in,
                              void* d_out, int out_size) {
    const float* x      = (const float*)d_in[0];
    const int*   ei     = (const int*)d_in[1];
    const int*   et     = (const int*)d_in[2];
    const float* W1     = (const float*)d_in[3];
    const float* root1  = (const float*)d_in[4];
    const float* bias1  = (const float*)d_in[5];
    const float* gamma1 = (const float*)d_in[6];
    const float* beta1  = (const float*)d_in[7];
    const float* W2     = (const float*)d_in[8];
    const float* root2  = (const float*)d_in[9];
    const float* bias2  = (const float*)d_in[10];
    const float* gamma2 = (const float*)d_in[11];
    const float* beta2  = (const float*)d_in[12];
    float*       out    = (float*)d_out;

    zero_kernel<<<1024, 256>>>();
    count_kernel<<<(EE + 255) / 256, 256>>>(ei, et);
    norm_kernel<<<(NR + 255) / 256, 256>>>();
    scatter1_kernel<<<(EE + 255) / 256, 256>>>(x, ei, et);   // norm folded in
    int mblocks = (NN + 127) / 128;
    transform1_tc<<<mblocks, 256>>>(x, W1, root1, bias1, gamma1, beta1);
    dim3 g2(mblocks, RR + 1);
    transform2_tc<<<g2, 256>>>(W2, root2);
    scatter2_kernel<<<(EE + 255) / 256, 256>>>(ei, et);
    final_ln<<<(NN * 16 + 255) / 256, 256>>>(bias2, gamma2, beta2, out);
}

// round 12
// speedup vs baseline: 1.1603x; 1.0189x over previous
#include <cuda_runtime.h>
#include <cstdint>

#define NN 50000
#define EE 800000
#define RR 8
#define DIN 64
#define DHID 128
#define DOUT 64
#define NR (NN*RR)
#define LN_EPS 1e-5f

// ---- scratch (device globals; no runtime allocation); 16B-aligned ----
__device__ __align__(16) float g_agg1[(size_t)NN*RR*DIN];  // pre-normalized sums
__device__ __align__(16) int   g_cnt[NR];
__device__ __align__(16) float g_h[(size_t)NN*DHID];
__device__ __align__(16) float g_hall[(size_t)RR*NN*DOUT];
__device__ __align__(16) float g_oagg[(size_t)NN*DOUT];

__device__ __forceinline__ uint32_t f2tf32(float f) {
    uint32_t v;
    asm("cvt.rna.tf32.f32 %0, %1;" : "=r"(v) : "f"(f));
    return v;
}

__device__ __forceinline__ void mma_tf32(float* c, uint32_t a0, uint32_t a1,
                                         uint32_t a2, uint32_t a3,
                                         uint32_t b0, uint32_t b1) {
    asm volatile(
        "mma.sync.aligned.m16n8k8.row.col.f32.tf32.tf32.f32 "
        "{%0,%1,%2,%3}, {%4,%5,%6,%7}, {%8,%9}, {%0,%1,%2,%3};"
        : "+f"(c[0]), "+f"(c[1]), "+f"(c[2]), "+f"(c[3])
        : "r"(a0), "r"(a1), "r"(a2), "r"(a3), "r"(b0), "r"(b1));
}

__device__ __forceinline__ void red4(float* p, float4 v) {
    asm volatile("red.global.add.v4.f32 [%0], {%1,%2,%3,%4};"
                 :: "l"(p), "f"(v.x), "f"(v.y), "f"(v.z), "f"(v.w) : "memory");
}

// 16B async copy; pred=false -> zero-fill
__device__ __forceinline__ void cp16(void* smem, const void* gmem, bool pred) {
    uint32_t s = (uint32_t)__cvta_generic_to_shared(smem);
    int sz = pred ? 16 : 0;
    asm volatile("cp.async.cg.shared.global [%0], [%1], 16, %2;"
                 :: "r"(s), "l"(gmem), "r"(sz));
}
__device__ __forceinline__ void cp_commit() {
    asm volatile("cp.async.commit_group;");
}

// ------------------------------------------------------------------
__global__ void zero_kernel() {
    size_t i = (size_t)blockIdx.x * blockDim.x + threadIdx.x;
    size_t n_agg1 = (size_t)NN * RR * DIN / 4;
    size_t stride = (size_t)gridDim.x * blockDim.x;
    float4 z = make_float4(0.f, 0.f, 0.f, 0.f);
    for (size_t k = i; k < n_agg1; k += stride)
        reinterpret_cast<float4*>(g_agg1)[k] = z;
    for (size_t k = i; k < NR; k += stride)
        g_cnt[k] = 0;
}

__global__ void count_kernel(const int* __restrict__ ei,
                             const int* __restrict__ et) {
    int e = blockIdx.x * blockDim.x + threadIdx.x;
    if (e < EE) atomicAdd(&g_cnt[ei[EE + e] * RR + et[e]], 1);
}

// ------------------------------------------------------------------
// layer-1 scatter, norm computed inline from cnt: agg1[dst,rel,:] += x[src,:]/cnt
__global__ void scatter1_kernel(const float* __restrict__ x,
                                const int* __restrict__ ei,
                                const int* __restrict__ et) {
    unsigned wid = (blockIdx.x * blockDim.x + threadIdx.x) >> 5;
    unsigned lane = threadIdx.x & 31;
    size_t e0 = (size_t)wid * 32;
    if (e0 >= EE) return;
    size_t my_e = e0 + lane;
    int s = ei[my_e];
    int d = ei[EE + my_e];
    int r = et[my_e];
    int c = g_cnt[d * RR + r];
    float nrm = c > 0 ? 1.0f / (float)c : 0.0f;

    unsigned half = lane >> 4;
    unsigned hl = lane & 15;
#pragma unroll 4
    for (int j = 0; j < 32; j += 2) {
        int sl = j + half;
        int sj = __shfl_sync(0xffffffffu, s, sl);
        int dj = __shfl_sync(0xffffffffu, d, sl);
        int rj = __shfl_sync(0xffffffffu, r, sl);
        float nj = __shfl_sync(0xffffffffu, nrm, sl);
        float4 v = *reinterpret_cast<const float4*>(x + (size_t)sj * DIN + hl * 4);
        v.x *= nj; v.y *= nj; v.z *= nj; v.w *= nj;
        red4(g_agg1 + ((size_t)dj * RR + rj) * DIN + hl * 4, v);
    }
}

// ------------------------------------------------------------------
// layer-1 transform (tf32, cp.async 2-stage): h = LN(leaky(Ahat@[W1;root1]+bias1))
// Ahat[n, k<512] = g_agg1 (pre-normalized); Ahat[n, 512+d] = x[n,d]. K=576.
__global__ __launch_bounds__(256) void transform1_tc(
    const float* __restrict__ x, const float* __restrict__ W1,
    const float* __restrict__ root1, const float* __restrict__ bias1,
    const float* __restrict__ gamma1, const float* __restrict__ beta1) {
    __shared__ __align__(16) float As[2][128][20];
    __shared__ __align__(16) float Bs[2][16][136];
    __shared__ float red_s[128][2];
    __shared__ float red_q[128][2];
    int tid = threadIdx.x;
    int m0 = blockIdx.x * 128;
    int lane = tid & 31, warp = tid >> 5;
    int warp_m = warp >> 1, warp_n = warp & 1;
    int qr = lane >> 2, qc = lane & 3;

    float acc[2][8][4];
#pragma unroll
    for (int mt = 0; mt < 2; mt++)
#pragma unroll
        for (int t = 0; t < 8; t++)
#pragma unroll
            for (int j = 0; j < 4; j++) acc[mt][t][j] = 0.f;

    int a_row = tid >> 1, a_c0 = (tid & 1) * 2;
    int b_row = tid >> 4, b_c0 = (tid & 15) * 2;
    bool a_valid = (m0 + a_row) < NN;

    auto issue = [&](int slab, int buf) {
#pragma unroll
        for (int i = 0; i < 2; i++) {
            int kg = slab * 16 + (a_c0 + i) * 4;
            const float* src = (kg < 512)
                ? g_agg1 + (size_t)(m0 + a_row) * 512 + kg
                : x + (size_t)(m0 + a_row) * 64 + (kg - 512);
            cp16(&As[buf][a_row][(a_c0 + i) * 4], src, a_valid);
        }
        {
            int kg = slab * 16 + b_row;
            const float* Brow = (kg < 512) ? (W1 + (size_t)kg * 128)
                                           : (root1 + (size_t)(kg - 512) * 128);
#pragma unroll
            for (int i = 0; i < 2; i++)
                cp16(&Bs[buf][b_row][(b_c0 + i) * 4], Brow + (b_c0 + i) * 4, true);
        }
        cp_commit();
    };

    const int NS = 36;
    issue(0, 0);
    for (int s = 0; s < NS; s++) {
        int buf = s & 1;
        if (s + 1 < NS) {
            issue(s + 1, (s + 1) & 1);
            asm volatile("cp.async.wait_group 1;");
        } else {
            asm volatile("cp.async.wait_group 0;");
        }
        __syncthreads();
#pragma unroll
        for (int k8 = 0; k8 < 2; k8++) {
            int k0 = k8 * 8;
            uint32_t a[2][4];
#pragma unroll
            for (int mt = 0; mt < 2; mt++) {
                int ar = warp_m * 32 + mt * 16 + qr;
                a[mt][0] = f2tf32(As[buf][ar][k0 + qc]);
                a[mt][1] = f2tf32(As[buf][ar + 8][k0 + qc]);
                a[mt][2] = f2tf32(As[buf][ar][k0 + qc + 4]);
                a[mt][3] = f2tf32(As[buf][ar + 8][k0 + qc + 4]);
            }
#pragma unroll
            for (int t = 0; t < 8; t++) {
                int cn = warp_n * 64 + t * 8 + qr;
                uint32_t b0 = f2tf32(Bs[buf][k0 + qc][cn]);
                uint32_t b1 = f2tf32(Bs[buf][k0 + qc + 4][cn]);
                mma_tf32(acc[0][t], a[0][0], a[0][1], a[0][2], a[0][3], b0, b1);
                mma_tf32(acc[1][t], a[1][0], a[1][1], a[1][2], a[1][3], b0, b1);
            }
        }
        __syncthreads();
    }

    // ---- epilogue: bias + LeakyReLU; cross-warp LN(128) ----
#pragma unroll
    for (int mt = 0; mt < 2; mt++) {
        float s[2] = {0.f, 0.f}, q[2] = {0.f, 0.f};
#pragma unroll
        for (int t = 0; t < 8; t++) {
            int c = warp_n * 64 + t * 8 + 2 * qc;
            float b0v = bias1[c], b1v = bias1[c + 1];
            float u;
            u = acc[mt][t][0] + b0v; u = u >= 0.f ? u : 0.2f * u; acc[mt][t][0] = u; s[0] += u; q[0] += u * u;
            u = acc[mt][t][1] + b1v; u = u >= 0.f ? u : 0.2f * u; acc[mt][t][1] = u; s[0] += u; q[0] += u * u;
            u = acc[mt][t][2] + b0v; u = u >= 0.f ? u : 0.2f * u; acc[mt][t][2] = u; s[1] += u; q[1] += u * u;
            u = acc[mt][t][3] + b1v; u = u >= 0.f ? u : 0.2f * u; acc[mt][t][3] = u; s[1] += u; q[1] += u * u;
        }
#pragma unroll
        for (int off = 1; off <= 2; off <<= 1) {
            s[0] += __shfl_xor_sync(0xffffffffu, s[0], off);
            q[0] += __shfl_xor_sync(0xffffffffu, q[0], off);
            s[1] += __shfl_xor_sync(0xffffffffu, s[1], off);
            q[1] += __shfl_xor_sync(0xffffffffu, q[1], off);
        }
        if (qc == 0) {
            int lr = warp_m * 32 + mt * 16 + qr;
            red_s[lr][warp_n] = s[0]; red_q[lr][warp_n] = q[0];
            red_s[lr + 8][warp_n] = s[1]; red_q[lr + 8][warp_n] = q[1];
        }
    }
    __syncthreads();
#pragma unroll
    for (int mt = 0; mt < 2; mt++) {
#pragma unroll
        for (int h = 0; h < 2; h++) {
            int lr = warp_m * 32 + mt * 16 + qr + 8 * h;
            int gm = m0 + lr;
            float S = red_s[lr][0] + red_s[lr][1];
            float Q = red_q[lr][0] + red_q[lr][1];
            float mu = S * (1.f / 128.f);
            float rstd = rsqrtf(Q * (1.f / 128.f) - mu * mu + LN_EPS);
            if (gm < NN) {
#pragma unroll
                for (int t = 0; t < 8; t++) {
                    int c = warp_n * 64 + t * 8 + 2 * qc;
                    float g0 = gamma1[c], g1 = gamma1[c + 1];
                    float e0 = beta1[c], e1 = beta1[c + 1];
                    *reinterpret_cast<float2*>(&g_h[(size_t)gm * 128 + c]) =
                        make_float2((acc[mt][t][2*h] - mu) * rstd * g0 + e0,
                                    (acc[mt][t][2*h+1] - mu) * rstd * g1 + e1);
                }
            }
        }
    }
}

// ------------------------------------------------------------------
// layer-2 transform (tf32, cp.async 2-stage), TWO relations per block.
// grid.y = ry in [0,5): ry<4 -> rels (2ry, 2ry+1) -> hall; ry==4 -> root2 -> oagg.
// Block tile 128(M) x 128(N): N-halves are the two W matrices; warp_n picks rel.
__global__ __launch_bounds__(256) void transform2_tc(const float* __restrict__ W2,
                                                     const float* __restrict__ root2) {
    __shared__ __align__(16) float As[2][128][20];
    __shared__ __align__(16) float Bs[2][16][136];
    int tid = threadIdx.x;
    int m0 = blockIdx.x * 128;
    int ry = blockIdx.y;
    bool dual = (ry < 4);
    const float* Wa = dual ? (W2 + (size_t)(2 * ry) * 128 * 64) : root2;
    const float* Wb = dual ? (W2 + (size_t)(2 * ry + 1) * 128 * 64) : root2;
    int lane = tid & 31, warp = tid >> 5;
    int warp_m = warp >> 1, warp_n = warp & 1;
    int qr = lane >> 2, qc = lane & 3;

    float acc[2][8][4];
#pragma unroll
    for (int mt = 0; mt < 2; mt++)
#pragma unroll
        for (int t = 0; t < 8; t++)
#pragma unroll
            for (int j = 0; j < 4; j++) acc[mt][t][j] = 0.f;

    int a_row = tid >> 1, a_c0 = (tid & 1) * 2;
    int b_row = tid >> 4, b_c0 = (tid & 15) * 2;   // chunks of 16B over 128 floats
    bool a_valid = (m0 + a_row) < NN;

    auto issue = [&](int slab, int buf) {
#pragma unroll
        for (int i = 0; i < 2; i++) {
            int kg = slab * 16 + (a_c0 + i) * 4;
            cp16(&As[buf][a_row][(a_c0 + i) * 4],
                 g_h + (size_t)(m0 + a_row) * 128 + kg, a_valid);
        }
        {
            int kg = slab * 16 + b_row;
#pragma unroll
            for (int i = 0; i < 2; i++) {
                int cc = b_c0 + i;   // 0..31
                const float* src = (cc < 16)
                    ? Wa + (size_t)kg * 64 + cc * 4
                    : Wb + (size_t)kg * 64 + (cc - 16) * 4;
                cp16(&Bs[buf][b_row][cc * 4], src, true);
            }
        }
        cp_commit();
    };

    const int NS = 8;
    issue(0, 0);
    for (int s = 0; s < NS; s++) {
        int buf = s & 1;
        if (s + 1 < NS) {
            issue(s + 1, (s + 1) & 1);
            asm volatile("cp.async.wait_group 1;");
        } else {
            asm volatile("cp.async.wait_group 0;");
        }
        __syncthreads();
#pragma unroll
        for (int k8 = 0; k8 < 2; k8++) {
            int k0 = k8 * 8;
            uint32_t a[2][4];
#pragma unroll
            for (int mt = 0; mt < 2; mt++) {
                int ar = warp_m * 32 + mt * 16 + qr;
                a[mt][0] = f2tf32(As[buf][ar][k0 + qc]);
                a[mt][1] = f2tf32(As[buf][ar + 8][k0 + qc]);
                a[mt][2] = f2tf32(As[buf][ar][k0 + qc + 4]);
                a[mt][3] = f2tf32(As[buf][ar + 8][k0 + qc + 4]);
            }
#pragma unroll
            for (int t = 0; t < 8; t++) {
                int cn = warp_n * 64 + t * 8 + qr;
                uint32_t b0 = f2tf32(Bs[buf][k0 + qc][cn]);
                uint32_t b1 = f2tf32(Bs[buf][k0 + qc + 4][cn]);
                mma_tf32(acc[0][t], a[0][0], a[0][1], a[0][2], a[0][3], b0, b1);
                mma_tf32(acc[1][t], a[1][0], a[1][1], a[1][2], a[1][3], b0, b1);
            }
        }
        __syncthreads();
    }

    // dst per warp_n: warp_n==0 -> rel a; warp_n==1 -> rel b (skip if !dual)
    float* dst;
    bool do_store;
    if (dual) {
        dst = g_hall + (size_t)(2 * ry + warp_n) * NN * 64;
        do_store = true;
    } else {
        dst = g_oagg;
        do_store = (warp_n == 0);   // both halves computed root2; store once
    }
    if (do_store) {
#pragma unroll
        for (int mt = 0; mt < 2; mt++) {
            int r1 = m0 + warp_m * 32 + mt * 16 + qr;
            int r2 = r1 + 8;
#pragma unroll
            for (int t = 0; t < 8; t++) {
                int c = t * 8 + 2 * qc;
                if (r1 < NN)
                    *reinterpret_cast<float2*>(dst + (size_t)r1 * 64 + c) =
                        make_float2(acc[mt][t][0], acc[mt][t][1]);
                if (r2 < NN)
                    *reinterpret_cast<float2*>(dst + (size_t)r2 * 64 + c) =
                        make_float2(acc[mt][t][2], acc[mt][t][3]);
            }
        }
    }
}

// ------------------------------------------------------------------
// layer-2 scatter: oagg[dst,:] += hall[rel,src,:]/cnt  (norm inline)
__global__ void scatter2_kernel(const int* __restrict__ ei,
                                const int* __restrict__ et) {
    unsigned wid = (blockIdx.x * blockDim.x + threadIdx.x) >> 5;
    unsigned lane = threadIdx.x & 31;
    size_t e0 = (size_t)wid * 32;
    if (e0 >= EE) return;
    size_t my_e = e0 + lane;
    int s = ei[my_e];
    int d = ei[EE + my_e];
    int r = et[my_e];
    int c = g_cnt[d * RR + r];
    float nrm = c > 0 ? 1.0f / (float)c : 0.0f;

    unsigned half = lane >> 4;
    unsigned hl = lane & 15;
#pragma unroll 4
    for (int j = 0; j < 32; j += 2) {
        int sl = j + half;
        int sj = __shfl_sync(0xffffffffu, s, sl);
        int dj = __shfl_sync(0xffffffffu, d, sl);
        int rj = __shfl_sync(0xffffffffu, r, sl);
        float nj = __shfl_sync(0xffffffffu, nrm, sl);
        float4 v = *reinterpret_cast<const float4*>(
            g_hall + ((size_t)rj * NN + sj) * 64 + hl * 4);
        v.x *= nj; v.y *= nj; v.z *= nj; v.w *= nj;
        red4(g_oagg + (size_t)dj * 64 + hl * 4, v);
    }
}

// ------------------------------------------------------------------
// final: out = LN(oagg + bias2)
__global__ void final_ln(const float* __restrict__ bias2,
                         const float* __restrict__ gamma2,
                         const float* __restrict__ beta2,
                         float* __restrict__ out) {
    int t = blockIdx.x * blockDim.x + threadIdx.x;
    int n = t >> 4, hl = t & 15;
    if (n >= NN) return;
    float4 v = *reinterpret_cast<const float4*>(g_oagg + (size_t)n * 64 + hl * 4);
    float4 b = *reinterpret_cast<const float4*>(bias2 + hl * 4);
    v.x += b.x; v.y += b.y; v.z += b.z; v.w += b.w;
    float s = v.x + v.y + v.z + v.w;
    float q = v.x * v.x + v.y * v.y + v.z * v.z + v.w * v.w;
#pragma unroll
    for (int off = 8; off; off >>= 1) {
        s += __shfl_xor_sync(0xffffffffu, s, off);
        q += __shfl_xor_sync(0xffffffffu, q, off);
    }
    float mu = s * (1.f / 64.f);
    float rstd = rsqrtf(q * (1.f / 64.f) - mu * mu + LN_EPS);
    float4 g = *reinterpret_cast<const float4*>(gamma2 + hl * 4);
    float4 e = *reinterpret_cast<const float4*>(beta2 + hl * 4);
    float4 o;
    o.x = (v.x - mu) * rstd * g.x + e.x;
    o.y = (v.y - mu) * rstd * g.y + e.y;
    o.z = (v.z - mu) * rstd * g.z + e.z;
    o.w = (v.w - mu) * rstd * g.w + e.w;
    *reinterpret_cast<float4*>(out + (size_t)n * 64 + hl * 4) = o;
}

// ------------------------------------------------------------------
extern "C" void kernel_launch(void* const* d_in, const int* in_sizes, int n_in,
                              void* d_out, int out_size) {
    const float* x      = (const float*)d_in[0];
    const int*   ei     = (const int*)d_in[1];
    const int*   et     = (const int*)d_in[2];
    const float* W1     = (const float*)d_in[3];
    const float* root1  = (const float*)d_in[4];
    const float* bias1  = (const float*)d_in[5];
    const float* gamma1 = (const float*)d_in[6];
    const float* beta1  = (const float*)d_in[7];
    const float* W2     = (const float*)d_in[8];
    const float* root2  = (const float*)d_in[9];
    const float* bias2  = (const float*)d_in[10];
    const float* gamma2 = (const float*)d_in[11];
    const float* beta2  = (const float*)d_in[12];
    float*       out    = (float*)d_out;

    zero_kernel<<<1024, 256>>>();
    count_kernel<<<(EE + 255) / 256, 256>>>(ei, et);
    scatter1_kernel<<<(EE + 255) / 256, 256>>>(x, ei, et);
    int mblocks = (NN + 127) / 128;
    transform1_tc<<<mblocks, 256>>>(x, W1, root1, bias1, gamma1, beta1);
    dim3 g2(mblocks, 5);   // 4 dual-relation blocks + root2 block
    transform2_tc<<<g2, 256>>>(W2, root2);
    scatter2_kernel<<<(EE + 255) / 256, 256>>>(ei, et);
    final_ln<<<(NN * 16 + 255) / 256, 256>>>(bias2, gamma2, beta2, out);
}